// round 1
// baseline (speedup 1.0000x reference)
#include <cuda_runtime.h>
#include <cuda_bf16.h>
#include <math.h>

// Problem shape (fixed by the dataset):
//   Q,K,V : [B=4, H=16, S=4096, D=64] float32, output same shape float32.
// Pipeline:
//   sw    = silu(V)*V
//   c     = cumsum_s(sw)
//   c_n   = c * rsqrt(mean_d(c^2)+1e-5)
//   r     = (||Q||+1e-8) + (||K||+1e-8) + 1
//   m     = c_n / r
//   out0  = V * (1 + silu(m))
//   out   = out0 * rsqrt(mean_d(out0^2)+1e-5)

#define BH      64
#define SEQ     4096
#define DIM     64
#define CHUNK   128
#define NCHUNK  (SEQ / CHUNK)      // 32
#define GROUPS  8
#define SPG     (CHUNK / GROUPS)   // 16

// Scratch for inter-chunk scan: [BH][NCHUNK][DIM] = 512 KB (static device mem,
// fully rewritten every launch -> deterministic).
__device__ float g_part[BH * NCHUNK * DIM];

__device__ __forceinline__ float sigmoidf_fast(float x) {
    return 1.0f / (1.0f + __expf(-x));
}

// ---------------------------------------------------------------------------
// Kernel 1: per-chunk sums of silu(v)*v, per d-channel.
// grid = BH*NCHUNK, block = (64, 4)
// ---------------------------------------------------------------------------
__global__ __launch_bounds__(256) void k_chunk_sums(const float* __restrict__ V) {
    int blk = blockIdx.x;
    int bh = blk / NCHUNK, ch = blk % NCHUNK;
    int d = threadIdx.x;            // 0..63
    int g = threadIdx.y;            // 0..3
    const float* vp = V + ((size_t)bh * SEQ + (size_t)ch * CHUNK) * DIM + d;

    float acc = 0.f;
    #pragma unroll 4
    for (int s = g; s < CHUNK; s += 4) {
        float v = vp[(size_t)s * DIM];
        acc += v * v * sigmoidf_fast(v);
    }
    __shared__ float red[4][DIM];
    red[g][d] = acc;
    __syncthreads();
    if (g == 0) {
        g_part[((size_t)bh * NCHUNK + ch) * DIM + d] =
            red[0][d] + red[1][d] + red[2][d] + red[3][d];
    }
}

// ---------------------------------------------------------------------------
// Kernel 2: exclusive scan over the 32 chunk partials per (bh, d).
// grid = BH, block = 64. Loads all 32 into registers (MLP), scans, stores.
// ---------------------------------------------------------------------------
__global__ __launch_bounds__(64) void k_chunk_scan() {
    int bh = blockIdx.x;
    int d = threadIdx.x;
    float* p = g_part + (size_t)bh * NCHUNK * DIM + d;
    float vals[NCHUNK];
    #pragma unroll
    for (int c = 0; c < NCHUNK; c++) vals[c] = p[(size_t)c * DIM];
    float run = 0.f;
    #pragma unroll
    for (int c = 0; c < NCHUNK; c++) {
        p[(size_t)c * DIM] = run;    // exclusive prefix
        run += vals[c];
    }
}

// ---------------------------------------------------------------------------
// Kernel 3: main fused kernel.
// grid = BH*NCHUNK, block = 512 (phase A: 64 d-lanes x 8 s-groups;
//                               phase B: 16 warps x 8 rows each)
// SMEM: c values 32 KB + group totals/offsets 4 KB  (static, <48 KB)
// ---------------------------------------------------------------------------
__global__ __launch_bounds__(512, 2) void k_main(const float* __restrict__ Q,
                                                 const float* __restrict__ K,
                                                 const float* __restrict__ V,
                                                 float* __restrict__ O) {
    __shared__ float c_s[CHUNK][DIM];     // 32 KB: intra-chunk cumsum (local)
    __shared__ float tot[GROUPS][DIM];    // group totals
    __shared__ float off[GROUPS][DIM];    // exclusive group offset + chunk base

    int blk = blockIdx.x;
    int bh = blk / NCHUNK, ch = blk % NCHUNK;
    size_t base = ((size_t)bh * SEQ + (size_t)ch * CHUNK) * DIM;
    int tid = threadIdx.x;

    // ---------------- Phase A: hierarchical intra-chunk cumsum ----------------
    {
        int d = tid & 63;          // channel
        int g = tid >> 6;          // s-group 0..7
        const float* vp = V + base + (size_t)(g * SPG) * DIM + d;
        float acc = 0.f;
        #pragma unroll
        for (int j = 0; j < SPG; j++) {
            float v = vp[(size_t)j * DIM];
            acc += v * v * sigmoidf_fast(v);
            c_s[g * SPG + j][d] = acc;          // local (group-relative) cumsum
        }
        tot[g][d] = acc;
        __syncthreads();
        // exclusive offset for this (g, d): chunk base prefix + lower groups
        float o = g_part[((size_t)bh * NCHUNK + ch) * DIM + d];
        #pragma unroll
        for (int gg = 0; gg < GROUPS; gg++) {
            if (gg < g) o += tot[gg][d];
        }
        off[g][d] = o;
        __syncthreads();
    }

    // ---------------- Phase B: per-row math, fully parallel ----------------
    int w = tid >> 5;         // warp 0..15
    int lane = tid & 31;
    int d0 = lane * 2;        // each lane owns 2 channels

    #pragma unroll 2
    for (int i = 0; i < 8; i++) {
        int s = w * 8 + i;                 // row within chunk
        int gg = s >> 4;                   // which s-group
        size_t row = base + (size_t)s * DIM + d0;

        float2 q = *(const float2*)(Q + row);
        float2 k = *(const float2*)(K + row);
        float2 v = *(const float2*)(V + row);
        float2 cl = *(const float2*)(&c_s[s][d0]);
        float2 co = *(const float2*)(&off[gg][d0]);
        float c0 = cl.x + co.x;
        float c1 = cl.y + co.y;

        float sq = q.x * q.x + q.y * q.y;
        float sk = k.x * k.x + k.y * k.y;
        float sc = c0 * c0 + c1 * c1;
        #pragma unroll
        for (int m = 16; m > 0; m >>= 1) {
            sq += __shfl_xor_sync(0xFFFFFFFFu, sq, m);
            sk += __shfl_xor_sync(0xFFFFFFFFu, sk, m);
            sc += __shfl_xor_sync(0xFFFFFFFFu, sc, m);
        }

        float rms_c = rsqrtf(sc * (1.0f / DIM) + 1e-5f);
        float r = sqrtf(sq) + sqrtf(sk) + 1.0f + 2e-8f;
        float scale = rms_c / r;                 // m = c * scale

        float m0 = c0 * scale;
        float m1 = c1 * scale;
        float o0 = v.x * (1.0f + m0 * sigmoidf_fast(m0));
        float o1 = v.y * (1.0f + m1 * sigmoidf_fast(m1));

        float so = o0 * o0 + o1 * o1;
        #pragma unroll
        for (int m = 16; m > 0; m >>= 1)
            so += __shfl_xor_sync(0xFFFFFFFFu, so, m);

        float rms_o = rsqrtf(so * (1.0f / DIM) + 1e-5f);
        float2 out;
        out.x = o0 * rms_o;
        out.y = o1 * rms_o;
        *(float2*)(O + row) = out;
    }
}

// ---------------------------------------------------------------------------
extern "C" void kernel_launch(void* const* d_in, const int* in_sizes, int n_in,
                              void* d_out, int out_size) {
    const float* Q = (const float*)d_in[0];
    const float* K = (const float*)d_in[1];
    const float* V = (const float*)d_in[2];
    float* O = (float*)d_out;

    dim3 b1(64, 4);
    k_chunk_sums<<<BH * NCHUNK, b1>>>(V);
    k_chunk_scan<<<BH, 64>>>();
    k_main<<<BH * NCHUNK, 512>>>(Q, K, V, O);
}

// round 2
// speedup vs baseline: 1.7502x; 1.7502x over previous
#include <cuda_runtime.h>
#include <math.h>

// Shapes fixed by dataset: Q,K,V,O : [4,16,4096,64] fp32.
// out = rmsnorm( V * (1 + silu( rmsnorm(cumsum_s(silu(V)*V)) / (||Q||+||K||+1) )) )
//
// Single-pass decoupled-lookback chunked scan:
//   grid = 64 bh * 32 chunks, 512 threads, chunk = 128 rows.
//   Phase A: intra-chunk cumsum (float4, hierarchical), publish chunk aggregate.
//   Lookback: sum predecessor aggregates (parallel, depth 1).
//   Phase B: per-row normalization math, 16-lane butterfly reductions.

#define BH      64
#define SEQ     4096
#define DIM     64
#define CHUNK   128
#define NCHUNK  32
#define NGRP    32            // groups of 4 rows inside a chunk
#define NBLK    (BH * NCHUNK)

__device__ float g_agg[NBLK * DIM];   // per-chunk aggregates of silu(v)*v
__device__ int   g_flag[NBLK];        // release flags (memset to 0 each launch)

__device__ __forceinline__ float sigf(float x) {
    return __fdividef(1.0f, 1.0f + __expf(-x));
}
__device__ __forceinline__ float4 add4(float4 a, float4 b) {
    return make_float4(a.x + b.x, a.y + b.y, a.z + b.z, a.w + b.w);
}
__device__ __forceinline__ float4 sw4(float4 v) {   // silu(v)*v = v*v*sigmoid(v)
    return make_float4(v.x * v.x * sigf(v.x), v.y * v.y * sigf(v.y),
                       v.z * v.z * sigf(v.z), v.w * v.w * sigf(v.w));
}
__device__ __forceinline__ int ld_acq(const int* p) {
    int v;
    asm volatile("ld.global.acquire.gpu.b32 %0, [%1];" : "=r"(v) : "l"(p) : "memory");
    return v;
}

extern "C" __global__ void __launch_bounds__(512, 2)
k_fused(const float* __restrict__ Q, const float* __restrict__ K,
        const float* __restrict__ V, float* __restrict__ O)
{
    __shared__ float4 c_s[CHUNK][16];   // 32 KB: group-local cumsum
    __shared__ float4 gsum[NGRP][16];   //  8 KB: inclusive group sums (scanned)
    __shared__ float4 goff[NGRP][16];   //  8 KB: final per-group offsets
    __shared__ float4 basev[16];        // chunk base prefix
    __shared__ float  pre[8][DIM];      // lookback partials

    const int blk = blockIdx.x;
    const int bh  = blk >> 5;
    const int ch  = blk & 31;
    const size_t cbase = ((size_t)bh * SEQ + (size_t)ch * CHUNK) * DIM;
    const int tid = threadIdx.x;

    // ---------------- Phase A: intra-chunk cumsum ----------------
    {
        const int q = tid & 15;          // d-quad (d0 = q*4)
        const int g = tid >> 4;          // group 0..31 (4 rows each)
        const float* vp = V + cbase + (size_t)(g * 4) * DIM + q * 4;
        float4 v0 = *(const float4*)(vp);
        float4 v1 = *(const float4*)(vp + DIM);
        float4 v2 = *(const float4*)(vp + 2 * DIM);
        float4 v3 = *(const float4*)(vp + 3 * DIM);

        float4 a0 = sw4(v0);
        float4 a1 = add4(a0, sw4(v1));
        float4 a2 = add4(a1, sw4(v2));
        float4 a3 = add4(a2, sw4(v3));
        c_s[g * 4 + 0][q] = a0;
        c_s[g * 4 + 1][q] = a1;
        c_s[g * 4 + 2][q] = a2;
        c_s[g * 4 + 3][q] = a3;
        gsum[g][q] = a3;
        __syncthreads();

        // Kogge-Stone inclusive scan over the 32 group sums
        float4 run = a3;
        #pragma unroll
        for (int st = 1; st < NGRP; st <<= 1) {
            float4 t = make_float4(0.f, 0.f, 0.f, 0.f);
            if (g >= st) t = gsum[g - st][q];
            __syncthreads();
            run = add4(run, t);
            gsum[g][q] = run;
            __syncthreads();
        }
    }

    // ---------------- Publish chunk aggregate ----------------
    if (tid < 16) {
        *(float4*)(g_agg + (size_t)blk * DIM + tid * 4) = gsum[NGRP - 1][tid];
        __threadfence();
    }
    __syncthreads();
    if (tid == 0) atomicExch(&g_flag[blk], 1);

    // ---------------- Lookback: sum predecessor aggregates ----------------
    if (ch > 0) {
        if (tid < ch) {                          // tid < ch <= 31 -> warp 0
            const int* fp = g_flag + (blk - ch) + tid;
            while (ld_acq(fp) == 0) __nanosleep(32);
        }
        __syncthreads();
        {
            const int d = tid & 63, j = tid >> 6;   // 8 lanes per channel
            float p = 0.f;
            for (int cc = j; cc < ch; cc += 8)
                p += __ldcg(g_agg + ((size_t)(bh * NCHUNK + cc)) * DIM + d);
            pre[j][d] = p;
        }
        __syncthreads();
        if (tid < 16) {
            float4 b = make_float4(0.f, 0.f, 0.f, 0.f);
            #pragma unroll
            for (int j = 0; j < 8; j++) {
                b.x += pre[j][tid * 4 + 0];
                b.y += pre[j][tid * 4 + 1];
                b.z += pre[j][tid * 4 + 2];
                b.w += pre[j][tid * 4 + 3];
            }
            basev[tid] = b;
        }
    } else {
        if (tid < 16) basev[tid] = make_float4(0.f, 0.f, 0.f, 0.f);
    }
    __syncthreads();

    // Per-group total offset = chunk base + exclusive group prefix
    {
        const int q = tid & 15, g = tid >> 4;
        float4 o = basev[q];
        if (g > 0) o = add4(o, gsum[g - 1][q]);
        goff[g][q] = o;
    }
    __syncthreads();

    // ---------------- Phase B: per-row math ----------------
    const int w    = tid >> 5;
    const int lane = tid & 31;
    const int half = lane >> 4;
    const int l    = lane & 15;          // lane owns channels 4l..4l+3

    #pragma unroll
    for (int it = 0; it < 4; it++) {
        const int s   = w * 8 + it * 2 + half;   // row within chunk
        const int grp = s >> 2;
        const size_t roff = cbase + (size_t)s * DIM + l * 4;

        float4 q4 = *(const float4*)(Q + roff);
        float4 k4 = *(const float4*)(K + roff);
        float4 v4 = *(const float4*)(V + roff);   // L1 hit (loaded in phase A)
        float4 c4 = add4(c_s[s][l], goff[grp][l]);

        float sq = q4.x * q4.x + q4.y * q4.y + q4.z * q4.z + q4.w * q4.w;
        float sk = k4.x * k4.x + k4.y * k4.y + k4.z * k4.z + k4.w * k4.w;
        float sc = c4.x * c4.x + c4.y * c4.y + c4.z * c4.z + c4.w * c4.w;
        #pragma unroll
        for (int m = 8; m; m >>= 1) {            // butterfly within 16 lanes
            sq += __shfl_xor_sync(0xFFFFFFFFu, sq, m);
            sk += __shfl_xor_sync(0xFFFFFFFFu, sk, m);
            sc += __shfl_xor_sync(0xFFFFFFFFu, sc, m);
        }

        float rms_c = rsqrtf(sc * (1.0f / DIM) + 1e-5f);
        float r     = sqrtf(sq) + sqrtf(sk) + 1.0f + 2e-8f;
        float scale = __fdividef(rms_c, r);      // m = c * scale

        float m0 = c4.x * scale, m1 = c4.y * scale;
        float m2 = c4.z * scale, m3 = c4.w * scale;
        float o0 = v4.x * (1.0f + m0 * sigf(m0));
        float o1 = v4.y * (1.0f + m1 * sigf(m1));
        float o2 = v4.z * (1.0f + m2 * sigf(m2));
        float o3 = v4.w * (1.0f + m3 * sigf(m3));

        float so = o0 * o0 + o1 * o1 + o2 * o2 + o3 * o3;
        #pragma unroll
        for (int m = 8; m; m >>= 1)
            so += __shfl_xor_sync(0xFFFFFFFFu, so, m);

        float rms_o = rsqrtf(so * (1.0f / DIM) + 1e-5f);
        float4 out = make_float4(o0 * rms_o, o1 * rms_o, o2 * rms_o, o3 * rms_o);
        *(float4*)(O + roff) = out;
    }
}

// ---------------------------------------------------------------------------
extern "C" void kernel_launch(void* const* d_in, const int* in_sizes, int n_in,
                              void* d_out, int out_size) {
    const float* Q = (const float*)d_in[0];
    const float* K = (const float*)d_in[1];
    const float* V = (const float*)d_in[2];
    float* O = (float*)d_out;

    void* fp = nullptr;
    cudaGetSymbolAddress(&fp, g_flag);
    cudaMemsetAsync(fp, 0, NBLK * sizeof(int), 0);

    k_fused<<<NBLK, 512>>>(Q, K, V, O);
}

// round 3
// speedup vs baseline: 1.8640x; 1.0650x over previous
#include <cuda_runtime.h>
#include <math.h>

// Q,K,V,O : [4,16,4096,64] fp32.
// out = rmsnorm( V * (1 + silu( rmsnorm(cumsum_s(silu(V)*V)) / (||Q||+||K||+1+2e-8) )) )
//
// Single-pass decoupled-lookback scan; Q/K norm computation overlapped with
// scan & lookback latency (Q,K are consumed only through their row L2-norms).

#define BH      64
#define SEQ     4096
#define DIM     64
#define CHUNK   128
#define NCHUNK  32
#define NGRP    32
#define NBLK    (BH * NCHUNK)

__device__ float g_agg[NBLK * DIM];
__device__ int   g_flag[NBLK];

__device__ __forceinline__ float sigf(float x) {
    return __fdividef(1.0f, 1.0f + __expf(-x));
}
__device__ __forceinline__ float4 add4(float4 a, float4 b) {
    return make_float4(a.x + b.x, a.y + b.y, a.z + b.z, a.w + b.w);
}
__device__ __forceinline__ float4 sw4(float4 v) {
    return make_float4(v.x * v.x * sigf(v.x), v.y * v.y * sigf(v.y),
                       v.z * v.z * sigf(v.z), v.w * v.w * sigf(v.w));
}
__device__ __forceinline__ float dot4(float4 a) {
    return a.x * a.x + a.y * a.y + a.z * a.z + a.w * a.w;
}
__device__ __forceinline__ int ld_acq(const int* p) {
    int v;
    asm volatile("ld.global.acquire.gpu.b32 %0, [%1];" : "=r"(v) : "l"(p) : "memory");
    return v;
}

extern "C" __global__ void __launch_bounds__(512, 2)
k_fused(const float* __restrict__ Q, const float* __restrict__ K,
        const float* __restrict__ V, float* __restrict__ O)
{
    __shared__ float4 c_s[CHUNK][16];   // 32 KB group-local cumsum
    __shared__ float4 gsum[NGRP][16];   //  8 KB group sums -> scanned -> offsets
    __shared__ float4 basev[16];        // chunk base prefix
    __shared__ float  pre[8][DIM];      // lookback partials

    const int blk = blockIdx.x;
    const int bh  = blk >> 5;
    const int ch  = blk & 31;
    const size_t cbase = ((size_t)bh * SEQ + (size_t)ch * CHUNK) * DIM;
    const int tid = threadIdx.x;

    // Phase-A mapping
    const int q = tid & 15;          // d-quad
    const int g = tid >> 4;          // row-group (4 rows)
    // Phase-B mapping
    const int w    = tid >> 5;
    const int lane = tid & 31;
    const int half = lane >> 4;
    const int l    = lane & 15;

    // ---------- Issue ALL global loads up front (V first: critical path) ----------
    const float* vp = V + cbase + (size_t)(g * 4) * DIM + q * 4;
    float4 v0 = *(const float4*)(vp);
    float4 v1 = *(const float4*)(vp + DIM);
    float4 v2 = *(const float4*)(vp + 2 * DIM);
    float4 v3 = *(const float4*)(vp + 3 * DIM);

    float4 qv[4], kv[4];
    #pragma unroll
    for (int it = 0; it < 4; it++) {
        const int s = w * 8 + it * 2 + half;
        const size_t roff = cbase + (size_t)s * DIM + l * 4;
        qv[it] = __ldcs((const float4*)(Q + roff));
        kv[it] = __ldcs((const float4*)(K + roff));
    }

    // ---------- Intra-chunk cumsum ----------
    float4 a0 = sw4(v0);
    float4 a1 = add4(a0, sw4(v1));
    float4 a2 = add4(a1, sw4(v2));
    float4 a3 = add4(a2, sw4(v3));
    c_s[g * 4 + 0][q] = a0;
    c_s[g * 4 + 1][q] = a1;
    c_s[g * 4 + 2][q] = a2;
    c_s[g * 4 + 3][q] = a3;
    gsum[g][q] = a3;
    __syncthreads();

    // Kogge-Stone over 32 group sums
    {
        float4 run = a3;
        #pragma unroll
        for (int st = 1; st < NGRP; st <<= 1) {
            float4 t = make_float4(0.f, 0.f, 0.f, 0.f);
            if (g >= st) t = gsum[g - st][q];
            __syncthreads();
            run = add4(run, t);
            gsum[g][q] = run;
            __syncthreads();
        }
    }

    // ---------- Publish aggregate + flag ASAP ----------
    if (tid < 16) {
        *(float4*)(g_agg + (size_t)blk * DIM + tid * 4) = gsum[NGRP - 1][tid];
        __threadfence();
    }
    __syncthreads();
    if (tid == 0) atomicExch(&g_flag[blk], 1);

    // ---------- Q/K row norms (overlaps lookback latency; warp-local only) ----------
    float r_row[4];
    #pragma unroll
    for (int it = 0; it < 4; it++) {
        float sq = dot4(qv[it]);
        float sk = dot4(kv[it]);
        #pragma unroll
        for (int m = 8; m; m >>= 1) {
            sq += __shfl_xor_sync(0xFFFFFFFFu, sq, m);
            sk += __shfl_xor_sync(0xFFFFFFFFu, sk, m);
        }
        r_row[it] = sqrtf(sq) + sqrtf(sk) + 1.0f + 2e-8f;
    }

    // ---------- Lookback ----------
    if (ch > 0) {
        if (tid < ch) {
            const int* fp = g_flag + (blk - ch) + tid;
            while (ld_acq(fp) == 0) __nanosleep(32);
        }
        __syncthreads();
        {
            const int d = tid & 63, j = tid >> 6;
            float p = 0.f;
            for (int cc = j; cc < ch; cc += 8)
                p += __ldcg(g_agg + ((size_t)(bh * NCHUNK + cc)) * DIM + d);
            pre[j][d] = p;
        }
        __syncthreads();
        if (tid < 16) {
            float4 b = make_float4(0.f, 0.f, 0.f, 0.f);
            #pragma unroll
            for (int j = 0; j < 8; j++) {
                b.x += pre[j][tid * 4 + 0];
                b.y += pre[j][tid * 4 + 1];
                b.z += pre[j][tid * 4 + 2];
                b.w += pre[j][tid * 4 + 3];
            }
            basev[tid] = b;
        }
    } else {
        if (tid < 16) basev[tid] = make_float4(0.f, 0.f, 0.f, 0.f);
    }
    __syncthreads();

    // Convert gsum (inclusive group scan) into per-group total offsets, in place.
    {
        float4 t = make_float4(0.f, 0.f, 0.f, 0.f);
        if (g > 0) t = gsum[g - 1][q];
        float4 b = basev[q];
        __syncthreads();
        gsum[g][q] = add4(b, t);
        __syncthreads();
    }

    // ---------- Phase B: per-row math ----------
    #pragma unroll
    for (int it = 0; it < 4; it++) {
        const int s   = w * 8 + it * 2 + half;
        const int grp = s >> 2;
        const size_t roff = cbase + (size_t)s * DIM + l * 4;

        float4 v4 = *(const float4*)(V + roff);        // L1 hit
        float4 c4 = add4(c_s[s][l], gsum[grp][l]);

        float sc = dot4(c4);
        #pragma unroll
        for (int m = 8; m; m >>= 1)
            sc += __shfl_xor_sync(0xFFFFFFFFu, sc, m);

        float rms_c = rsqrtf(sc * (1.0f / DIM) + 1e-5f);
        float scale = __fdividef(rms_c, r_row[it]);

        float m0 = c4.x * scale, m1 = c4.y * scale;
        float m2 = c4.z * scale, m3 = c4.w * scale;
        float o0 = v4.x * (1.0f + m0 * sigf(m0));
        float o1 = v4.y * (1.0f + m1 * sigf(m1));
        float o2 = v4.z * (1.0f + m2 * sigf(m2));
        float o3 = v4.w * (1.0f + m3 * sigf(m3));

        float so = o0 * o0 + o1 * o1 + o2 * o2 + o3 * o3;
        #pragma unroll
        for (int m = 8; m; m >>= 1)
            so += __shfl_xor_sync(0xFFFFFFFFu, so, m);

        float rms_o = rsqrtf(so * (1.0f / DIM) + 1e-5f);
        float4 out = make_float4(o0 * rms_o, o1 * rms_o, o2 * rms_o, o3 * rms_o);
        __stcs((float4*)(O + roff), out);
    }
}

// ---------------------------------------------------------------------------
extern "C" void kernel_launch(void* const* d_in, const int* in_sizes, int n_in,
                              void* d_out, int out_size) {
    const float* Q = (const float*)d_in[0];
    const float* K = (const float*)d_in[1];
    const float* V = (const float*)d_in[2];
    float* O = (float*)d_out;

    void* fp = nullptr;
    cudaGetSymbolAddress(&fp, g_flag);
    cudaMemsetAsync(fp, 0, NBLK * sizeof(int), 0);

    k_fused<<<NBLK, 512>>>(Q, K, V, O);
}

// round 4
// speedup vs baseline: 1.8933x; 1.0157x over previous
#include <cuda_runtime.h>
#include <math.h>

// Q,K,V,O : [4,16,4096,64] fp32.
// out = rmsnorm( V * (1 + silu( rmsnorm(cumsum_s(silu(V)*V)) / (||Q||+||K||+1+2e-8) )) )
//
// Decoupled-lookback scan, 256-thread CTAs, CHUNK=64 rows, warp-shuffle
// cross-group scan (no block Kogge-Stone), high occupancy.

#define BH      64
#define SEQ     4096
#define DIM     64
#define CHUNK   64
#define NCHUNK  64
#define NGRP    16              // groups of 4 rows
#define NBLK    (BH * NCHUNK)   // 4096

__device__ float g_agg[NBLK * DIM];
__device__ int   g_flag[NBLK];

__device__ __forceinline__ float sigf(float x) {
    return __fdividef(1.0f, 1.0f + __expf(-x));
}
__device__ __forceinline__ float4 add4(float4 a, float4 b) {
    return make_float4(a.x + b.x, a.y + b.y, a.z + b.z, a.w + b.w);
}
__device__ __forceinline__ float4 sw4(float4 v) {
    return make_float4(v.x * v.x * sigf(v.x), v.y * v.y * sigf(v.y),
                       v.z * v.z * sigf(v.z), v.w * v.w * sigf(v.w));
}
__device__ __forceinline__ float dot4(float4 a) {
    return a.x * a.x + a.y * a.y + a.z * a.z + a.w * a.w;
}
__device__ __forceinline__ int ld_acq(const int* p) {
    int v;
    asm volatile("ld.global.acquire.gpu.b32 %0, [%1];" : "=r"(v) : "l"(p) : "memory");
    return v;
}

extern "C" __global__ void __launch_bounds__(256, 5)
k_fused(const float* __restrict__ Q, const float* __restrict__ K,
        const float* __restrict__ V, float* __restrict__ O)
{
    __shared__ float4 c_s[CHUNK][16];      // 16 KB: group-local cumsum
    __shared__ float  gs[NGRP][68];        // 4.25 KB: group sums (transpose buf)
    __shared__ float  offs[NGRP][68];      // 4.25 KB: per-group total offsets
    __shared__ float4 basev[16];           // chunk base prefix
    __shared__ float  pre[4][DIM];         // 1 KB lookback partials

    const int blk = blockIdx.x;
    const int bh  = blk >> 6;
    const int ch  = blk & 63;
    const size_t cbase = ((size_t)bh * SEQ + (size_t)ch * CHUNK) * DIM;
    const int tid  = threadIdx.x;
    const int lane = tid & 31;
    const int w    = tid >> 5;             // warp 0..7

    // ---------------- Phase A: per-group cumsum (4 rows/thread) ----------------
    {
        const int q = tid & 15;            // d-quad
        const int g = tid >> 4;            // group 0..15
        const float* vp = V + cbase + (size_t)(g * 4) * DIM + q * 4;
        float4 v0 = *(const float4*)(vp);
        float4 v1 = *(const float4*)(vp + DIM);
        float4 v2 = *(const float4*)(vp + 2 * DIM);
        float4 v3 = *(const float4*)(vp + 3 * DIM);

        float4 a0 = sw4(v0);
        float4 a1 = add4(a0, sw4(v1));
        float4 a2 = add4(a1, sw4(v2));
        float4 a3 = add4(a2, sw4(v3));
        c_s[g * 4 + 0][q] = a0;
        c_s[g * 4 + 1][q] = a1;
        c_s[g * 4 + 2][q] = a2;
        c_s[g * 4 + 3][q] = a3;
        *(float4*)&gs[g][q * 4] = a3;      // transposed view for the scan
    }
    __syncthreads();

    // ---------------- Warp-shuffle scan over 16 group sums ----------------
    const int seg = lane >> 4;             // segment within warp
    const int sl  = lane & 15;             // group index in scan
    const int qq  = w * 2 + seg;           // d-quad this scan lane handles

    float4 incl = *(const float4*)&gs[sl][qq * 4];
    #pragma unroll
    for (int st = 1; st < 16; st <<= 1) {
        float4 t;
        t.x = __shfl_up_sync(0xFFFFFFFFu, incl.x, st);
        t.y = __shfl_up_sync(0xFFFFFFFFu, incl.y, st);
        t.z = __shfl_up_sync(0xFFFFFFFFu, incl.z, st);
        t.w = __shfl_up_sync(0xFFFFFFFFu, incl.w, st);
        if (sl >= st) incl = add4(incl, t);
    }

    // Publish chunk aggregate ASAP (lane 15 of each segment holds it)
    if (sl == 15) {
        *(float4*)(g_agg + (size_t)blk * DIM + qq * 4) = incl;
        __threadfence();
    }
    __syncthreads();
    if (tid == 0) atomicExch(&g_flag[blk], 1);

    // Exclusive prefix (shift by one lane; exact)
    float4 excl;
    excl.x = __shfl_up_sync(0xFFFFFFFFu, incl.x, 1);
    excl.y = __shfl_up_sync(0xFFFFFFFFu, incl.y, 1);
    excl.z = __shfl_up_sync(0xFFFFFFFFu, incl.z, 1);
    excl.w = __shfl_up_sync(0xFFFFFFFFu, incl.w, 1);
    if (sl == 0) excl = make_float4(0.f, 0.f, 0.f, 0.f);

    // ---------------- Lookback ----------------
    if (ch > 0) {
        if (tid < ch) {                    // up to 63 pollers (warps 0-1)
            const int* fp = g_flag + bh * NCHUNK + tid;
            while (ld_acq(fp) == 0) __nanosleep(32);
        }
        __syncthreads();
        {
            const int d = tid & 63, j = tid >> 6;   // 4 partials per channel
            float p = 0.f;
            for (int cc = j; cc < ch; cc += 4)
                p += __ldcg(g_agg + ((size_t)(bh * NCHUNK + cc)) * DIM + d);
            pre[j][d] = p;
        }
        __syncthreads();
        if (tid < 16) {
            float4 b;
            b.x = pre[0][tid*4+0] + pre[1][tid*4+0] + pre[2][tid*4+0] + pre[3][tid*4+0];
            b.y = pre[0][tid*4+1] + pre[1][tid*4+1] + pre[2][tid*4+1] + pre[3][tid*4+1];
            b.z = pre[0][tid*4+2] + pre[1][tid*4+2] + pre[2][tid*4+2] + pre[3][tid*4+2];
            b.w = pre[0][tid*4+3] + pre[1][tid*4+3] + pre[2][tid*4+3] + pre[3][tid*4+3];
            basev[tid] = b;
        }
    } else {
        if (tid < 16) basev[tid] = make_float4(0.f, 0.f, 0.f, 0.f);
    }
    __syncthreads();

    // Per-group total offset = chunk base + exclusive group prefix
    {
        float4 o = add4(excl, basev[qq]);
        *(float4*)&offs[sl][qq * 4] = o;
    }
    __syncthreads();

    // ---------------- Phase B: per-row math ----------------
    const int half = lane >> 4;
    const int l    = lane & 15;            // lane owns channels 4l..4l+3

    #pragma unroll
    for (int it = 0; it < 4; it++) {
        const int s   = w * 8 + it * 2 + half;   // row within chunk
        const int grp = s >> 2;
        const size_t roff = cbase + (size_t)s * DIM + l * 4;

        float4 q4 = __ldcs((const float4*)(Q + roff));
        float4 k4 = __ldcs((const float4*)(K + roff));
        float4 v4 = *(const float4*)(V + roff);         // L1 hit
        float4 c4 = add4(c_s[s][l], *(const float4*)&offs[grp][l * 4]);

        float sq = dot4(q4);
        float sk = dot4(k4);
        float sc = dot4(c4);
        #pragma unroll
        for (int m = 8; m; m >>= 1) {
            sq += __shfl_xor_sync(0xFFFFFFFFu, sq, m);
            sk += __shfl_xor_sync(0xFFFFFFFFu, sk, m);
            sc += __shfl_xor_sync(0xFFFFFFFFu, sc, m);
        }

        float rms_c = rsqrtf(sc * (1.0f / DIM) + 1e-5f);
        float r     = sqrtf(sq) + sqrtf(sk) + 1.0f + 2e-8f;
        float scale = __fdividef(rms_c, r);

        float m0 = c4.x * scale, m1 = c4.y * scale;
        float m2 = c4.z * scale, m3 = c4.w * scale;
        float o0 = v4.x * (1.0f + m0 * sigf(m0));
        float o1 = v4.y * (1.0f + m1 * sigf(m1));
        float o2 = v4.z * (1.0f + m2 * sigf(m2));
        float o3 = v4.w * (1.0f + m3 * sigf(m3));

        float so = o0 * o0 + o1 * o1 + o2 * o2 + o3 * o3;
        #pragma unroll
        for (int m = 8; m; m >>= 1)
            so += __shfl_xor_sync(0xFFFFFFFFu, so, m);

        float rms_o = rsqrtf(so * (1.0f / DIM) + 1e-5f);
        float4 out = make_float4(o0 * rms_o, o1 * rms_o, o2 * rms_o, o3 * rms_o);
        __stcs((float4*)(O + roff), out);
    }
}

// ---------------------------------------------------------------------------
extern "C" void kernel_launch(void* const* d_in, const int* in_sizes, int n_in,
                              void* d_out, int out_size) {
    const float* Q = (const float*)d_in[0];
    const float* K = (const float*)d_in[1];
    const float* V = (const float*)d_in[2];
    float* O = (float*)d_out;

    void* fp = nullptr;
    cudaGetSymbolAddress(&fp, g_flag);
    cudaMemsetAsync(fp, 0, NBLK * sizeof(int), 0);

    k_fused<<<NBLK, 256>>>(Q, K, V, O);
}